// round 3
// baseline (speedup 1.0000x reference)
#include <cuda_runtime.h>

#define NUM_GRAPHS 1024
#define KPT 32            // nodes per thread
#define TPB 256

__device__ float  g_Sr[NUM_GRAPHS * 3];
__device__ double g_sumq;

__global__ void init_kernel(float* out) {
    int i = blockIdx.x * blockDim.x + threadIdx.x;
    if (i < NUM_GRAPHS * 3) {
        out[i]  = 0.0f;
        g_Sr[i] = 0.0f;
    }
    if (i == 0) g_sumq = 0.0;
}

__device__ __forceinline__ void flush_seg(float* __restrict__ out, int cur,
                                          float ax, float ay, float az,
                                          float rx, float ry, float rz) {
    atomicAdd(&out[cur * 3 + 0], ax);
    atomicAdd(&out[cur * 3 + 1], ay);
    atomicAdd(&out[cur * 3 + 2], az);
    atomicAdd(&g_Sr[cur * 3 + 0], rx);
    atomicAdd(&g_Sr[cur * 3 + 1], ry);
    atomicAdd(&g_Sr[cur * 3 + 2], rz);
}

__global__ void polar_main(const float* __restrict__ pos,
                           const float* __restrict__ q,
                           const int* __restrict__ batch,
                           float* __restrict__ out,
                           long long n) {
    long long t    = (long long)blockIdx.x * blockDim.x + threadIdx.x;
    long long base = t * KPT;

    float ax = 0.f, ay = 0.f, az = 0.f;   // S_qr accumulators
    float rx = 0.f, ry = 0.f, rz = 0.f;   // S_r accumulators
    float qs = 0.f;
    int   cur = -1;

    if (base < n) {
        cur = batch[base];

        if (base + KPT <= n) {
            // fast path: fully vectorized, 16B-aligned
            const float4* q4 = reinterpret_cast<const float4*>(q + base);
            const float4* p4 = reinterpret_cast<const float4*>(pos + base * 3);
            const int4*   b4 = reinterpret_cast<const int4*>(batch + base);

            #pragma unroll
            for (int j = 0; j < KPT / 4; j++) {
                float4 qv = q4[j];
                float4 pa = p4[3 * j + 0];
                float4 pb = p4[3 * j + 1];
                float4 pc = p4[3 * j + 2];
                int4   gv = b4[j];

                int   g[4]  = {gv.x, gv.y, gv.z, gv.w};
                float px[4] = {pa.x, pa.w, pb.z, pc.y};
                float py[4] = {pa.y, pb.x, pb.w, pc.z};
                float pz[4] = {pa.z, pb.y, pc.x, pc.w};
                float qq[4] = {qv.x, qv.y, qv.z, qv.w};

                #pragma unroll
                for (int m = 0; m < 4; m++) {
                    if (g[m] != cur) {            // segment boundary (rare)
                        flush_seg(out, cur, ax, ay, az, rx, ry, rz);
                        ax = ay = az = rx = ry = rz = 0.f;
                        cur = g[m];
                    }
                    qs += qq[m];
                    ax = fmaf(qq[m], px[m], ax);
                    ay = fmaf(qq[m], py[m], ay);
                    az = fmaf(qq[m], pz[m], az);
                    rx += px[m];
                    ry += py[m];
                    rz += pz[m];
                }
            }
        } else {
            // tail path (scalar)
            for (long long i = base; i < n; i++) {
                int g = batch[i];
                if (g != cur) {
                    flush_seg(out, cur, ax, ay, az, rx, ry, rz);
                    ax = ay = az = rx = ry = rz = 0.f;
                    cur = g;
                }
                float qi = q[i];
                float x  = pos[i * 3 + 0];
                float y  = pos[i * 3 + 1];
                float z  = pos[i * 3 + 2];
                qs += qi;
                ax = fmaf(qi, x, ax);
                ay = fmaf(qi, y, ay);
                az = fmaf(qi, z, az);
                rx += x; ry += y; rz += z;
            }
        }
        // final flush for this thread's last open segment
        flush_seg(out, cur, ax, ay, az, rx, ry, rz);
    }

    // block-level reduction of qs, then one double atomic per block
    __shared__ float sm[TPB];
    sm[threadIdx.x] = qs;
    __syncthreads();
    #pragma unroll
    for (int s = TPB / 2; s > 0; s >>= 1) {
        if (threadIdx.x < s) sm[threadIdx.x] += sm[threadIdx.x + s];
        __syncthreads();
    }
    if (threadIdx.x == 0) atomicAdd(&g_sumq, (double)sm[0]);
}

__global__ void finalize_kernel(float* out, double inv_n) {
    int i = blockIdx.x * blockDim.x + threadIdx.x;
    if (i < NUM_GRAPHS * 3) {
        float mean = (float)(g_sumq * inv_n);
        out[i] = out[i] - mean * g_Sr[i];
    }
}

extern "C" void kernel_launch(void* const* d_in, const int* in_sizes, int n_in,
                              void* d_out, int out_size) {
    const float* pos   = (const float*)d_in[0];
    const float* q     = (const float*)d_in[1];
    const int*   batch = (const int*)d_in[2];
    float*       out   = (float*)d_out;

    long long n = in_sizes[1];               // number of nodes (q element count)

    // init: zero accumulators + output (graph replays re-run everything)
    init_kernel<<<(NUM_GRAPHS * 3 + TPB - 1) / TPB, TPB>>>(out);

    long long nthreads = (n + KPT - 1) / KPT;
    int       nblocks  = (int)((nthreads + TPB - 1) / TPB);
    polar_main<<<nblocks, TPB>>>(pos, q, batch, out, n);

    finalize_kernel<<<(NUM_GRAPHS * 3 + TPB - 1) / TPB, TPB>>>(out, 1.0 / (double)n);
}

// round 5
// speedup vs baseline: 3.4241x; 3.4241x over previous
#include <cuda_runtime.h>

#define NUM_GRAPHS 1024
#define TPB 256
#define NBLOCKS 1024   // 8192 warps total

__device__ float  g_Sr[NUM_GRAPHS * 3];
__device__ double g_sumq;

__global__ void init_kernel(float* out) {
    int i = blockIdx.x * blockDim.x + threadIdx.x;
    if (i < NUM_GRAPHS * 3) {
        out[i]  = 0.0f;
        g_Sr[i] = 0.0f;
    }
    if (i == 0) g_sumq = 0.0;
}

__device__ __forceinline__ void warp_reduce6(float& a0, float& a1, float& a2,
                                             float& a3, float& a4, float& a5) {
    #pragma unroll
    for (int s = 16; s > 0; s >>= 1) {
        a0 += __shfl_down_sync(0xffffffffu, a0, s);
        a1 += __shfl_down_sync(0xffffffffu, a1, s);
        a2 += __shfl_down_sync(0xffffffffu, a2, s);
        a3 += __shfl_down_sync(0xffffffffu, a3, s);
        a4 += __shfl_down_sync(0xffffffffu, a4, s);
        a5 += __shfl_down_sync(0xffffffffu, a5, s);
    }
}

__device__ __forceinline__ void atomic6(float* __restrict__ out, int seg,
                                        float ax, float ay, float az,
                                        float rx, float ry, float rz) {
    atomicAdd(&out[seg * 3 + 0], ax);
    atomicAdd(&out[seg * 3 + 1], ay);
    atomicAdd(&out[seg * 3 + 2], az);
    atomicAdd(&g_Sr[seg * 3 + 0], rx);
    atomicAdd(&g_Sr[seg * 3 + 1], ry);
    atomicAdd(&g_Sr[seg * 3 + 2], rz);
}

__global__ void polar_main(const float* __restrict__ pos,
                           const float* __restrict__ q,
                           const int* __restrict__ batch,
                           float* __restrict__ out,
                           long long n, long long chunk) {
    const int lane = threadIdx.x & 31;
    const long long warpId = ((long long)blockIdx.x * blockDim.x + threadIdx.x) >> 5;
    const long long start  = warpId * chunk;

    float qs = 0.f;

    if (start < n) {
        long long end = start + chunk; if (end > n) end = n;
        const long long nE = end - start;
        const long long nG = nE >> 2;        // full 4-element groups
        const int       r  = (int)(nE & 3);  // tail elements

        const int segFirst = batch[start];
        const int segLast  = batch[end - 1];

        // start is a multiple of 4 -> q+start is 16B aligned, pos+start*3 is 48B aligned
        const float4* q4 = reinterpret_cast<const float4*>(q + start);
        const float4* p4 = reinterpret_cast<const float4*>(pos + start * 3);

        float ax = 0.f, ay = 0.f, az = 0.f, rx = 0.f, ry = 0.f, rz = 0.f;

        if (segFirst == segLast) {
            // ---- fast path: whole chunk is one segment; no batch loads ----
            #pragma unroll 4
            for (long long c = lane; c < nG; c += 32) {
                float4 qv = q4[c];
                float4 pa = p4[3 * c + 0];
                float4 pb = p4[3 * c + 1];
                float4 pc = p4[3 * c + 2];
                qs += (qv.x + qv.y) + (qv.z + qv.w);
                ax = fmaf(qv.x, pa.x, ax); ax = fmaf(qv.y, pa.w, ax);
                ax = fmaf(qv.z, pb.z, ax); ax = fmaf(qv.w, pc.y, ax);
                ay = fmaf(qv.x, pa.y, ay); ay = fmaf(qv.y, pb.x, ay);
                ay = fmaf(qv.z, pb.w, ay); ay = fmaf(qv.w, pc.z, ay);
                az = fmaf(qv.x, pa.z, az); az = fmaf(qv.y, pb.y, az);
                az = fmaf(qv.z, pc.x, az); az = fmaf(qv.w, pc.w, az);
                rx += (pa.x + pa.w) + (pb.z + pc.y);
                ry += (pa.y + pb.x) + (pb.w + pc.z);
                rz += (pa.z + pb.y) + (pc.x + pc.w);
            }
            if (lane < r) {
                long long i = start + (nG << 2) + lane;
                float qi = q[i];
                float x = pos[i * 3 + 0], y = pos[i * 3 + 1], z = pos[i * 3 + 2];
                qs += qi;
                ax = fmaf(qi, x, ax); ay = fmaf(qi, y, ay); az = fmaf(qi, z, az);
                rx += x; ry += y; rz += z;
            }
            warp_reduce6(ax, ay, az, rx, ry, rz);
            if (lane == 0) atomic6(out, segFirst, ax, ay, az, rx, ry, rz);
        } else {
            // ---- mixed path (rare): chunk straddes >=1 boundary ----
            const int4* b4 = reinterpret_cast<const int4*>(batch + start);
            float bx = 0.f, by = 0.f, bz = 0.f, sx = 0.f, sy = 0.f, sz = 0.f;

            #pragma unroll 2
            for (long long c = lane; c < nG; c += 32) {
                float4 qv = q4[c];
                int4   gv = b4[c];
                float4 pa = p4[3 * c + 0];
                float4 pb = p4[3 * c + 1];
                float4 pc = p4[3 * c + 2];
                int   g[4]  = {gv.x, gv.y, gv.z, gv.w};
                float qq[4] = {qv.x, qv.y, qv.z, qv.w};
                float px[4] = {pa.x, pa.w, pb.z, pc.y};
                float py[4] = {pa.y, pb.x, pb.w, pc.z};
                float pz[4] = {pa.z, pb.y, pc.x, pc.w};
                #pragma unroll
                for (int m = 0; m < 4; m++) {
                    qs += qq[m];
                    if (g[m] == segFirst) {
                        ax = fmaf(qq[m], px[m], ax); ay = fmaf(qq[m], py[m], ay);
                        az = fmaf(qq[m], pz[m], az);
                        rx += px[m]; ry += py[m]; rz += pz[m];
                    } else if (g[m] == segLast) {
                        bx = fmaf(qq[m], px[m], bx); by = fmaf(qq[m], py[m], by);
                        bz = fmaf(qq[m], pz[m], bz);
                        sx += px[m]; sy += py[m]; sz += pz[m];
                    } else {
                        atomic6(out, g[m], qq[m] * px[m], qq[m] * py[m],
                                qq[m] * pz[m], px[m], py[m], pz[m]);
                    }
                }
            }
            if (lane < r) {
                long long i = start + (nG << 2) + lane;
                int   g  = batch[i];
                float qi = q[i];
                float x = pos[i * 3 + 0], y = pos[i * 3 + 1], z = pos[i * 3 + 2];
                qs += qi;
                if (g == segFirst) {
                    ax = fmaf(qi, x, ax); ay = fmaf(qi, y, ay); az = fmaf(qi, z, az);
                    rx += x; ry += y; rz += z;
                } else if (g == segLast) {
                    bx = fmaf(qi, x, bx); by = fmaf(qi, y, by); bz = fmaf(qi, z, bz);
                    sx += x; sy += y; sz += z;
                } else {
                    atomic6(out, g, qi * x, qi * y, qi * z, x, y, z);
                }
            }
            warp_reduce6(ax, ay, az, rx, ry, rz);
            warp_reduce6(bx, by, bz, sx, sy, sz);
            if (lane == 0) {
                atomic6(out, segFirst, ax, ay, az, rx, ry, rz);
                atomic6(out, segLast,  bx, by, bz, sx, sy, sz);
            }
        }
    }

    // ---- block reduction of qs, one double atomic per block ----
    __shared__ float sm[TPB];
    sm[threadIdx.x] = qs;
    __syncthreads();
    #pragma unroll
    for (int s = TPB / 2; s > 0; s >>= 1) {
        if (threadIdx.x < s) sm[threadIdx.x] += sm[threadIdx.x + s];
        __syncthreads();
    }
    if (threadIdx.x == 0) atomicAdd(&g_sumq, (double)sm[0]);
}

__global__ void finalize_kernel(float* out, double inv_n) {
    int i = blockIdx.x * blockDim.x + threadIdx.x;
    if (i < NUM_GRAPHS * 3) {
        float mean = (float)(g_sumq * inv_n);
        out[i] = out[i] - mean * g_Sr[i];
    }
}

extern "C" void kernel_launch(void* const* d_in, const int* in_sizes, int n_in,
                              void* d_out, int out_size) {
    const float* pos   = (const float*)d_in[0];
    const float* q     = (const float*)d_in[1];
    const int*   batch = (const int*)d_in[2];
    float*       out   = (float*)d_out;

    long long n = in_sizes[1];

    long long totalWarps = (long long)NBLOCKS * TPB / 32;
    long long chunk = ((n + totalWarps - 1) / totalWarps + 3) & ~3LL;  // multiple of 4

    init_kernel<<<(NUM_GRAPHS * 3 + TPB - 1) / TPB, TPB>>>(out);
    polar_main<<<NBLOCKS, TPB>>>(pos, q, batch, out, n, chunk);
    finalize_kernel<<<(NUM_GRAPHS * 3 + TPB - 1) / TPB, TPB>>>(out, 1.0 / (double)n);
}